// round 11
// baseline (speedup 1.0000x reference)
#include <cuda_runtime.h>
#include <cuda_fp16.h>

#define BDIM   4
#define SLEN   2048
#define DMODEL 512
#define HNUM   8
#define KDIM   64
#define BSROWS (BDIM * SLEN)   // 8192
#define NBH    (BDIM * HNUM)   // 32

// ---------------- scratch (static device globals, all fp16-as-ushort) ----------------
__device__ __align__(16) unsigned short g_xf[BSROWS * DMODEL];          // x
__device__ __align__(16) unsigned short g_wtf[24 * KDIM * DMODEL];      // [hj][n][d]
__device__ __align__(16) unsigned short g_hktf[DMODEL * DMODEL];        // [n][e]
__device__ __align__(16) unsigned short g_qf[NBH * SLEN * KDIM];        // [bh][s][d] (pre-scaled 1/8)
__device__ __align__(16) unsigned short g_kf[NBH * SLEN * KDIM];        // [bh][t][d]
__device__ __align__(16) unsigned short g_vtf[NBH * KDIM * SLEN];       // [bh][d][t]
__device__ __align__(16) unsigned short g_cf[BSROWS * DMODEL];          // concat [row][e]

// ---------------- helpers ----------------
__device__ __forceinline__ unsigned smem_u32(const void* p) {
    unsigned a;
    asm("{ .reg .u64 t; cvta.to.shared.u64 t, %1; cvt.u32.u64 %0, t; }" : "=r"(a) : "l"(p));
    return a;
}
#define CP16(dst, src) \
    asm volatile("cp.async.cg.shared.global [%0], [%1], 16;" :: "r"(dst), "l"(src))
#define CPCOMMIT() asm volatile("cp.async.commit_group;" ::: "memory")
#define CPWAIT0()  asm volatile("cp.async.wait_group 0;" ::: "memory")
#define CPWAIT1()  asm volatile("cp.async.wait_group 1;" ::: "memory")

__device__ __forceinline__ void ldsm4(unsigned* r, unsigned a) {
    asm volatile("ldmatrix.sync.aligned.m8n8.x4.shared.b16 {%0,%1,%2,%3}, [%4];"
        : "=r"(r[0]), "=r"(r[1]), "=r"(r[2]), "=r"(r[3]) : "r"(a));
}
// A operand m16 x k16 at (m0, kbyte), row-major smem, stride bytes
__device__ __forceinline__ void ldA(unsigned* r, unsigned base, int stride, int m0, int kb, int lane) {
    int row = m0 + (lane & 7) + ((lane >> 3) & 1) * 8;
    int col = kb + (lane >> 4) * 16;
    ldsm4(r, base + row * stride + col);
}
// B operand: two n8 tiles (n0, n0+8) x k16 at kbyte
__device__ __forceinline__ void ldB(unsigned* r, unsigned base, int stride, int n0, int kb, int lane) {
    int row = n0 + (lane & 7) + (lane >> 4) * 8;
    int col = kb + ((lane >> 3) & 1) * 16;
    ldsm4(r, base + row * stride + col);
}
__device__ __forceinline__ void mma_fp16(float* c, const unsigned* a, unsigned b0, unsigned b1) {
    asm volatile("mma.sync.aligned.m16n8k16.row.col.f32.f16.f16.f32 "
        "{%0,%1,%2,%3}, {%4,%5,%6,%7}, {%8,%9}, {%0,%1,%2,%3};"
        : "+f"(c[0]), "+f"(c[1]), "+f"(c[2]), "+f"(c[3])
        : "r"(a[0]), "r"(a[1]), "r"(a[2]), "r"(a[3]), "r"(b0), "r"(b1));
}
__device__ __forceinline__ unsigned short f2h(float x) {
    __half v = __float2half_rn(x);
    return *(unsigned short*)&v;
}
__device__ __forceinline__ unsigned pk2(unsigned short a, unsigned short b) {
    return (unsigned)a | ((unsigned)b << 16);
}

// ================= convert kernels =================
__global__ void convert_x(const float* __restrict__ src, int n4) {
    int i = blockIdx.x * blockDim.x + threadIdx.x;
    if (i >= n4) return;
    float4 v = ((const float4*)src)[i];
    ((uint2*)g_xf)[i] = make_uint2(pk2(f2h(v.x), f2h(v.y)), pk2(f2h(v.z), f2h(v.w)));
}
// w: [24][512][64] -> [24][64][512] fp16
__global__ void transpose_w(const float* __restrict__ src, int nwork) {
    int i = blockIdx.x * blockDim.x + threadIdx.x;
    if (i >= nwork) return;
    int n = i % 64, rest = i / 64;
    int d8 = rest & 63, mat = rest >> 6;
    int d0 = d8 * 8;
    unsigned short h[8];
#pragma unroll
    for (int j = 0; j < 8; j++)
        h[j] = f2h(src[(size_t)mat * 512 * 64 + (size_t)(d0 + j) * 64 + n]);
    size_t dst = (size_t)mat * 64 * 512 + (size_t)n * 512 + d0;
    *(uint4*)(g_wtf + dst) = make_uint4(pk2(h[0],h[1]), pk2(h[2],h[3]), pk2(h[4],h[5]), pk2(h[6],h[7]));
}
// hk: [512][512] -> transposed fp16
__global__ void transpose_hk(const float* __restrict__ src, int nwork) {
    int i = blockIdx.x * blockDim.x + threadIdx.x;
    if (i >= nwork) return;
    int n = i % 512, d8 = i / 512;
    int d0 = d8 * 8;
    unsigned short h[8];
#pragma unroll
    for (int j = 0; j < 8; j++)
        h[j] = f2h(src[(size_t)(d0 + j) * 512 + n]);
    size_t dst = (size_t)n * 512 + d0;
    *(uint4*)(g_hktf + dst) = make_uint4(pk2(h[0],h[1]), pk2(h[2],h[3]), pk2(h[4],h[5]), pk2(h[6],h[7]));
}

// ================= QKV projection (fp16 1-pass, 512 thr, cp.async 2-stage) =================
// grid (64, 8), block 512. C[128x192] = x[128x512] . wt_head[192x512]^T.
// 16 warps as 8m x 2n: warp tile 16 x 96 (acc 48 floats).
// stage (46080 B): A 0 (18432 = 128x144), B 18432 (27648 = 192x144)
#define QSTG 46080
#define QKV_SMEM (2 * QSTG)     // 92160
__global__ __launch_bounds__(512, 1) void qkv_mma() {
    extern __shared__ char smc[];
    const unsigned sb = smem_u32(smc);
    const int tid = threadIdx.x, wid = tid >> 5, lane = tid & 31;
    const int wm = wid >> 1, wn = wid & 1;
    const int h = blockIdx.y, row0 = blockIdx.x * 128;
    const int m0 = wm * 16, n0 = wn * 96;

    auto issue = [&](int c8) {
        const unsigned ab = sb + (c8 & 1) * QSTG;
        const int d0 = c8 * 64;
#pragma unroll
        for (int t = 0; t < 2; t++) {               // A: 128 rows x 8 x 16B
            int idx = tid + t * 512, r = idx >> 3, q = idx & 7;
            CP16(ab + r * 144 + q * 16, g_xf + (size_t)(row0 + r) * 512 + d0 + q * 8);
        }
#pragma unroll
        for (int t = 0; t < 3; t++) {               // B: 192 rows
            int idx = tid + t * 512, r = idx >> 3, q = idx & 7;
            CP16(ab + 18432 + r * 144 + q * 16, g_wtf + (size_t)(h * 192 + r) * 512 + d0 + q * 8);
        }
    };

    float acc[12][4];
#pragma unroll
    for (int n = 0; n < 12; n++)
#pragma unroll
        for (int c = 0; c < 4; c++) acc[n][c] = 0.f;

    issue(0); CPCOMMIT();
    for (int c8 = 0; c8 < 8; c8++) {
        if (c8 < 7) { issue(c8 + 1); CPCOMMIT(); CPWAIT1(); } else { CPWAIT0(); }
        __syncthreads();
        const unsigned ab = sb + (c8 & 1) * QSTG;
#pragma unroll
        for (int ks = 0; ks < 4; ks++) {
            const int kb = ks * 32;
            unsigned af[4];
            ldA(af, ab, 144, m0, kb, lane);
#pragma unroll
            for (int g = 0; g < 6; g++) {
                unsigned bf[4];
                ldB(bf, ab + 18432, 144, n0 + g * 16, kb, lane);
                mma_fp16(acc[2*g],   af, bf[0], bf[1]);
                mma_fp16(acc[2*g+1], af, bf[2], bf[3]);
            }
        }
        __syncthreads();
    }

    // writeout: q,k direct; v staged transposed into stage-0 region (free)
#pragma unroll
    for (int half = 0; half < 2; half++) {
        int tl = m0 + half * 8 + (lane >> 2);       // local row 0..127
        int r = row0 + tl;
        int b = r >> 11, s = r & (SLEN - 1);
#pragma unroll
        for (int nt = 0; nt < 12; nt++) {
            int col = n0 + nt * 8 + (lane & 3) * 2;
            int j = col >> 6, cc = col & 63;
            float v0 = acc[nt][half * 2 + 0];
            float v1 = acc[nt][half * 2 + 1];
            if (j == 0) { v0 *= 0.125f; v1 *= 0.125f; }
            if (j < 2) {
                unsigned short* dst = (j == 0) ? g_qf : g_kf;
                size_t base = ((size_t)(b * HNUM + h) * SLEN + s) * KDIM + cc;
                *(unsigned*)(dst + base) = pk2(f2h(v0), f2h(v1));
            } else {   // V: [d][t] into stage 0
                *(unsigned short*)(smc + (cc    ) * 272 + tl * 2) = f2h(v0);
                *(unsigned short*)(smc + (cc + 1) * 272 + tl * 2) = f2h(v1);
            }
        }
    }
    __syncthreads();
    {
        const int b = row0 >> 11, s0 = row0 & (SLEN - 1);
        const size_t vbase = ((size_t)(b * HNUM + h) * KDIM) * SLEN;
#pragma unroll
        for (int t = 0; t < 2; t++) {
            int idx = tid + t * 512, d = idx >> 4, q = idx & 15;
            *(uint4*)(g_vtf + vbase + (size_t)d * SLEN + s0 + q * 8) =
                *(const uint4*)(smc + d * 272 + q * 16);
        }
    }
}

// ================= attention (fp16, 512 thr, key-split warp groups) =================
// grid (16, 32), block 512. Warp wid: wg = wid>>3 (key half), wr = wid&7 (q-rows 16wr..+15).
// smem: Q 0 (18432); stage s at 18432 + s*35840: K +0 (18432), V +18432 (17408).
// O/l exchange overlays the stage region after the loop (128x272B + 512B).
#define ASTG0 18432
#define ASTG  35840
#define ATT_SMEM (ASTG0 + 2 * ASTG)   // 90112
__global__ __launch_bounds__(512, 1) void attn_mma() {
    extern __shared__ char smc[];
    const unsigned sb = smem_u32(smc);
    const int tid = threadIdx.x, wid = tid >> 5, lane = tid & 31;
    const int wg = wid >> 3, wr = wid & 7;
    const int m0 = wr * 16, nh = wg * 64;   // key-col half offset
    const int bh = blockIdx.y, q0 = blockIdx.x * 128;
    const int b = bh >> 3, h = bh & 7;

    const size_t kbase = (size_t)bh * SLEN * KDIM;
    const size_t vbase = (size_t)bh * KDIM * SLEN;

    auto issue_kv = [&](int it) {
        const unsigned stb = sb + ASTG0 + (it & 1) * ASTG;
        const int t0 = it * 128;
#pragma unroll
        for (int t = 0; t < 2; t++) {                 // K tile [t][d]
            int idx = tid + t * 512, r = idx >> 3, q = idx & 7;
            CP16(stb + r * 144 + q * 16, g_kf + kbase + (size_t)(t0 + r) * KDIM + q * 8);
        }
#pragma unroll
        for (int t = 0; t < 2; t++) {                 // Vt tile [d][t]
            int idx = tid + t * 512, d = idx >> 4, q = idx & 15;
            CP16(stb + 18432 + d * 272 + q * 16, g_vtf + vbase + (size_t)d * SLEN + t0 + q * 8);
        }
    };

    // prologue: Q + stage 0
    {
        const size_t qb = ((size_t)bh * SLEN + q0) * KDIM;
#pragma unroll
        for (int t = 0; t < 2; t++) {
            int idx = tid + t * 512, r = idx >> 3, q = idx & 7;
            CP16(sb + r * 144 + q * 16, g_qf + qb + (size_t)r * KDIM + q * 8);
        }
        issue_kv(0); CPCOMMIT();
    }

    float oacc[8][4];
    float ls0 = 0.f, ls1 = 0.f;
#pragma unroll
    for (int n = 0; n < 8; n++)
#pragma unroll
        for (int c = 0; c < 4; c++) oacc[n][c] = 0.f;

    for (int it = 0; it < 16; it++) {
        if (it < 15) { issue_kv(it + 1); CPCOMMIT(); CPWAIT1(); } else { CPWAIT0(); }
        __syncthreads();
        const unsigned stb = sb + ASTG0 + (it & 1) * ASTG;

        // ---- S = Q K^T : this warp's 64-key half ----
        float sacc[8][4];
#pragma unroll
        for (int n = 0; n < 8; n++)
#pragma unroll
            for (int c = 0; c < 4; c++) sacc[n][c] = 0.f;
#pragma unroll
        for (int ks = 0; ks < 4; ks++) {
            const int kb = ks * 32;
            unsigned aq[4];
            ldA(aq, sb, 144, m0, kb, lane);
#pragma unroll
            for (int g = 0; g < 4; g++) {
                unsigned bk[4];
                ldB(bk, stb, 144, nh + g * 16, kb, lane);
                mma_fp16(sacc[2*g],   aq, bk[0], bk[1]);
                mma_fp16(sacc[2*g+1], aq, bk[2], bk[3]);
            }
        }

        // ---- p = exp(s); pack P as fp16 A-fragments; rowsum of ROUNDED p ----
        unsigned ph[4][4];
#pragma unroll
        for (int nt = 0; nt < 8; nt++) {
            float p0 = __expf(sacc[nt][0]);
            float p1 = __expf(sacc[nt][1]);
            float p2 = __expf(sacc[nt][2]);
            float p3 = __expf(sacc[nt][3]);
            __half2 ha = __floats2half2_rn(p0, p1);
            __half2 hb = __floats2half2_rn(p2, p3);
            float2 fa = __half22float2(ha);
            float2 fb = __half22float2(hb);
            ls0 += fa.x + fa.y;
            ls1 += fb.x + fb.y;
            int kc = nt >> 1, o = (nt & 1) * 2;
            ph[kc][o]     = *(unsigned*)&ha;
            ph[kc][o + 1] = *(unsigned*)&hb;
        }

        // ---- O += P V over this warp's key half ----
#pragma unroll
        for (int kc = 0; kc < 4; kc++) {
            const int kb = nh * 2 + kc * 32;
#pragma unroll
            for (int g = 0; g < 4; g++) {
                unsigned bf[4];
                ldB(bf, stb + 18432, 272, g * 16, kb, lane);
                mma_fp16(oacc[2*g],   ph[kc], bf[0], bf[1]);
                mma_fp16(oacc[2*g+1], ph[kc], bf[2], bf[3]);
            }
        }
        __syncthreads();
    }

    // ---- rowsum quad-reduce ----
    ls0 += __shfl_xor_sync(0xffffffffu, ls0, 1);
    ls0 += __shfl_xor_sync(0xffffffffu, ls0, 2);
    ls1 += __shfl_xor_sync(0xffffffffu, ls1, 1);
    ls1 += __shfl_xor_sync(0xffffffffu, ls1, 2);

    // ---- combine the two key-half partials via smem (stage region is dead) ----
    float* ox = (float*)(smc + ASTG0);                  // [128][68] fp32
    float* lx = (float*)(smc + ASTG0 + 34816);          // [128]
    const int r = m0 + (lane >> 2);
    if (wg == 1) {
#pragma unroll
        for (int nt = 0; nt < 8; nt++) {
            int col = nt * 8 + (lane & 3) * 2;
            ox[(r    ) * 68 + col]     = oacc[nt][0];
            ox[(r    ) * 68 + col + 1] = oacc[nt][1];
            ox[(r + 8) * 68 + col]     = oacc[nt][2];
            ox[(r + 8) * 68 + col + 1] = oacc[nt][3];
        }
        if ((lane & 3) == 0) { lx[r] = ls0; lx[r + 8] = ls1; }
    }
    __syncthreads();
    if (wg == 0) {
        const float inv0 = 1.f / (ls0 + lx[r]);
        const float inv1 = 1.f / (ls1 + lx[r + 8]);
        const size_t base0 = ((size_t)b * SLEN + q0 + r) * DMODEL + h * KDIM;
        const size_t base1 = base0 + 8 * DMODEL;
#pragma unroll
        for (int nt = 0; nt < 8; nt++) {
            int col = nt * 8 + (lane & 3) * 2;
            float v0 = (oacc[nt][0] + ox[(r    ) * 68 + col])     * inv0;
            float v1 = (oacc[nt][1] + ox[(r    ) * 68 + col + 1]) * inv0;
            float v2 = (oacc[nt][2] + ox[(r + 8) * 68 + col])     * inv1;
            float v3 = (oacc[nt][3] + ox[(r + 8) * 68 + col + 1]) * inv1;
            *(unsigned*)(g_cf + base0 + col) = pk2(f2h(v0), f2h(v1));
            *(unsigned*)(g_cf + base1 + col) = pk2(f2h(v2), f2h(v3));
        }
    }
}

// ================= output projection (fp16 1-pass, 512 thr, cp.async 2-stage) =================
// grid (64, 4), block 512. 16 warps as 8m x 2n: warp tile 16 x 64.
// stage: A 0 (18432), B 18432 (18432)
#define OSTG 36864
#define OUT_SMEM (2 * OSTG)     // 73728
__global__ __launch_bounds__(512, 1) void outproj_mma(float* __restrict__ out) {
    extern __shared__ char smc[];
    const unsigned sb = smem_u32(smc);
    const int tid = threadIdx.x, wid = tid >> 5, lane = tid & 31;
    const int wm = wid >> 1, wn = wid & 1;
    const int row0 = blockIdx.x * 128, n0 = blockIdx.y * 128;
    const int m0 = wm * 16, nw = wn * 64;

    auto issue = [&](int c8) {
        const unsigned ob = sb + (c8 & 1) * OSTG;
        const int e0 = c8 * 64;
#pragma unroll
        for (int t = 0; t < 2; t++) {
            int idx = tid + t * 512, r = idx >> 3, q = idx & 7;
            CP16(ob + r * 144 + q * 16, g_cf + (size_t)(row0 + r) * 512 + e0 + q * 8);
            CP16(ob + 18432 + r * 144 + q * 16, g_hktf + (size_t)(n0 + r) * 512 + e0 + q * 8);
        }
    };

    float acc[8][4];
#pragma unroll
    for (int n = 0; n < 8; n++)
#pragma unroll
        for (int c = 0; c < 4; c++) acc[n][c] = 0.f;

    issue(0); CPCOMMIT();
    for (int c8 = 0; c8 < 8; c8++) {
        if (c8 < 7) { issue(c8 + 1); CPCOMMIT(); CPWAIT1(); } else { CPWAIT0(); }
        __syncthreads();
        const unsigned ob = sb + (c8 & 1) * OSTG;
#pragma unroll
        for (int ks = 0; ks < 4; ks++) {
            const int kb = ks * 32;
            unsigned af[4];
            ldA(af, ob, 144, m0, kb, lane);
#pragma unroll
            for (int g = 0; g < 4; g++) {
                unsigned bf[4];
                ldB(bf, ob + 18432, 144, nw + g * 16, kb, lane);
                mma_fp16(acc[2*g],   af, bf[0], bf[1]);
                mma_fp16(acc[2*g+1], af, bf[2], bf[3]);
            }
        }
        __syncthreads();
    }

    {
        int r0 = row0 + m0 + (lane >> 2);
#pragma unroll
        for (int hf = 0; hf < 2; hf++) {
            size_t base = (size_t)(r0 + hf * 8) * DMODEL + n0;
#pragma unroll
            for (int nt = 0; nt < 8; nt++) {
                int col = nw + nt * 8 + (lane & 3) * 2;
                out[base + col]     = acc[nt][hf * 2 + 0];
                out[base + col + 1] = acc[nt][hf * 2 + 1];
            }
        }
    }
}

// =====================================================================
extern "C" void kernel_launch(void* const* d_in, const int* in_sizes, int n_in,
                              void* d_out, int out_size)
{
    const float* x    = (const float*)d_in[0];   // (4, 2048, 512)
    const float* kern = (const float*)d_in[1];   // (24, 512, 64)
    const float* hk   = (const float*)d_in[2];   // (512, 512)
    float* out = (float*)d_out;                  // (4, 2048, 512)

    cudaFuncSetAttribute(qkv_mma,     cudaFuncAttributeMaxDynamicSharedMemorySize, QKV_SMEM);
    cudaFuncSetAttribute(attn_mma,    cudaFuncAttributeMaxDynamicSharedMemorySize, ATT_SMEM);
    cudaFuncSetAttribute(outproj_mma, cudaFuncAttributeMaxDynamicSharedMemorySize, OUT_SMEM);

    const int n4x = BSROWS * DMODEL / 4;                     // 1048576
    convert_x<<<(n4x + 255) / 256, 256>>>(x, n4x);
    transpose_w<<<(24 * 64 * 64 + 255) / 256, 256>>>(kern, 24 * 64 * 64);
    transpose_hk<<<(64 * 512 + 255) / 256, 256>>>(hk, 64 * 512);

    qkv_mma<<<dim3(BSROWS / 128, HNUM), 512, QKV_SMEM>>>();
    attn_mma<<<dim3(SLEN / 128, NBH), 512, ATT_SMEM>>>();
    outproj_mma<<<dim3(BSROWS / 128, DMODEL / 128), 512, OUT_SMEM>>>(out);
}

// round 13
// speedup vs baseline: 1.0836x; 1.0836x over previous
#include <cuda_runtime.h>
#include <cuda_fp16.h>

#define BDIM   4
#define SLEN   2048
#define DMODEL 512
#define HNUM   8
#define KDIM   64
#define BSROWS (BDIM * SLEN)   // 8192
#define NBH    (BDIM * HNUM)   // 32

// ---------------- scratch (static device globals, all fp16-as-ushort) ----------------
__device__ __align__(16) unsigned short g_xf[BSROWS * DMODEL];          // x
__device__ __align__(16) unsigned short g_wtf[24 * KDIM * DMODEL];      // [hj][n][d]
__device__ __align__(16) unsigned short g_hktf[DMODEL * DMODEL];        // [n][e]
__device__ __align__(16) unsigned short g_qf[NBH * SLEN * KDIM];        // [bh][s][d] (pre-scaled 1/8)
__device__ __align__(16) unsigned short g_kf[NBH * SLEN * KDIM];        // [bh][t][d]
__device__ __align__(16) unsigned short g_vtf[NBH * KDIM * SLEN];       // [bh][d][t]
__device__ __align__(16) unsigned short g_cf[BSROWS * DMODEL];          // concat [row][e]

// ---------------- helpers ----------------
__device__ __forceinline__ unsigned smem_u32(const void* p) {
    unsigned a;
    asm("{ .reg .u64 t; cvta.to.shared.u64 t, %1; cvt.u32.u64 %0, t; }" : "=r"(a) : "l"(p));
    return a;
}
#define CP16(dst, src) \
    asm volatile("cp.async.cg.shared.global [%0], [%1], 16;" :: "r"(dst), "l"(src))
#define CPCOMMIT() asm volatile("cp.async.commit_group;" ::: "memory")
#define CPWAIT0()  asm volatile("cp.async.wait_group 0;" ::: "memory")
#define CPWAIT1()  asm volatile("cp.async.wait_group 1;" ::: "memory")

__device__ __forceinline__ void ldsm4(unsigned* r, unsigned a) {
    asm volatile("ldmatrix.sync.aligned.m8n8.x4.shared.b16 {%0,%1,%2,%3}, [%4];"
        : "=r"(r[0]), "=r"(r[1]), "=r"(r[2]), "=r"(r[3]) : "r"(a));
}
// A operand m16 x k16 at (m0, kbyte), row-major smem, stride bytes
__device__ __forceinline__ void ldA(unsigned* r, unsigned base, int stride, int m0, int kb, int lane) {
    int row = m0 + (lane & 7) + ((lane >> 3) & 1) * 8;
    int col = kb + (lane >> 4) * 16;
    ldsm4(r, base + row * stride + col);
}
// B operand: two n8 tiles (n0, n0+8) x k16 at kbyte
__device__ __forceinline__ void ldB(unsigned* r, unsigned base, int stride, int n0, int kb, int lane) {
    int row = n0 + (lane & 7) + (lane >> 4) * 8;
    int col = kb + ((lane >> 3) & 1) * 16;
    ldsm4(r, base + row * stride + col);
}
__device__ __forceinline__ void mma_fp16(float* c, const unsigned* a, unsigned b0, unsigned b1) {
    asm volatile("mma.sync.aligned.m16n8k16.row.col.f32.f16.f16.f32 "
        "{%0,%1,%2,%3}, {%4,%5,%6,%7}, {%8,%9}, {%0,%1,%2,%3};"
        : "+f"(c[0]), "+f"(c[1]), "+f"(c[2]), "+f"(c[3])
        : "r"(a[0]), "r"(a[1]), "r"(a[2]), "r"(a[3]), "r"(b0), "r"(b1));
}
__device__ __forceinline__ unsigned short f2h(float x) {
    __half v = __float2half_rn(x);
    return *(unsigned short*)&v;
}
__device__ __forceinline__ unsigned pk2(unsigned short a, unsigned short b) {
    return (unsigned)a | ((unsigned)b << 16);
}

// ================= convert kernels =================
__global__ void convert_x(const float* __restrict__ src, int n4) {
    int i = blockIdx.x * blockDim.x + threadIdx.x;
    if (i >= n4) return;
    float4 v = ((const float4*)src)[i];
    ((uint2*)g_xf)[i] = make_uint2(pk2(f2h(v.x), f2h(v.y)), pk2(f2h(v.z), f2h(v.w)));
}
// w: [24][512][64] -> [24][64][512] fp16
__global__ void transpose_w(const float* __restrict__ src, int nwork) {
    int i = blockIdx.x * blockDim.x + threadIdx.x;
    if (i >= nwork) return;
    int n = i % 64, rest = i / 64;
    int d8 = rest & 63, mat = rest >> 6;
    int d0 = d8 * 8;
    unsigned short h[8];
#pragma unroll
    for (int j = 0; j < 8; j++)
        h[j] = f2h(src[(size_t)mat * 512 * 64 + (size_t)(d0 + j) * 64 + n]);
    size_t dst = (size_t)mat * 64 * 512 + (size_t)n * 512 + d0;
    *(uint4*)(g_wtf + dst) = make_uint4(pk2(h[0],h[1]), pk2(h[2],h[3]), pk2(h[4],h[5]), pk2(h[6],h[7]));
}
// hk: [512][512] -> transposed fp16
__global__ void transpose_hk(const float* __restrict__ src, int nwork) {
    int i = blockIdx.x * blockDim.x + threadIdx.x;
    if (i >= nwork) return;
    int n = i % 512, d8 = i / 512;
    int d0 = d8 * 8;
    unsigned short h[8];
#pragma unroll
    for (int j = 0; j < 8; j++)
        h[j] = f2h(src[(size_t)(d0 + j) * 512 + n]);
    size_t dst = (size_t)n * 512 + d0;
    *(uint4*)(g_hktf + dst) = make_uint4(pk2(h[0],h[1]), pk2(h[2],h[3]), pk2(h[4],h[5]), pk2(h[6],h[7]));
}

// ================= QKV projection (R10 config: fp16 1-pass, 256 thr) =================
// grid (64, 8), block 256. C[128x192] = x[128x512] . wt_head[192x512]^T.
// 8 warps as 4m x 2n: warp tile 32 x 96.
// stage (46080 B): A 0 (18432 = 128x144), B 18432 (27648 = 192x144)
#define QSTG 46080
#define QKV_SMEM (2 * QSTG)     // 92160
__global__ __launch_bounds__(256, 1) void qkv_mma() {
    extern __shared__ char smc[];
    const unsigned sb = smem_u32(smc);
    const int tid = threadIdx.x, wid = tid >> 5, lane = tid & 31;
    const int wm = wid >> 1, wn = wid & 1;
    const int h = blockIdx.y, row0 = blockIdx.x * 128;
    const int m0 = wm * 32, n0 = wn * 96;

    auto issue = [&](int c8) {
        const unsigned ab = sb + (c8 & 1) * QSTG;
        const int d0 = c8 * 64;
#pragma unroll
        for (int t = 0; t < 4; t++) {               // A: 128 rows x 8 x 16B
            int idx = tid + t * 256, r = idx >> 3, q = idx & 7;
            CP16(ab + r * 144 + q * 16, g_xf + (size_t)(row0 + r) * 512 + d0 + q * 8);
        }
#pragma unroll
        for (int t = 0; t < 6; t++) {               // B: 192 rows
            int idx = tid + t * 256, r = idx >> 3, q = idx & 7;
            CP16(ab + 18432 + r * 144 + q * 16, g_wtf + (size_t)(h * 192 + r) * 512 + d0 + q * 8);
        }
    };

    float acc[2][12][4];
#pragma unroll
    for (int a = 0; a < 2; a++)
#pragma unroll
        for (int n = 0; n < 12; n++)
#pragma unroll
            for (int c = 0; c < 4; c++) acc[a][n][c] = 0.f;

    issue(0); CPCOMMIT();
    for (int c8 = 0; c8 < 8; c8++) {
        if (c8 < 7) { issue(c8 + 1); CPCOMMIT(); CPWAIT1(); } else { CPWAIT0(); }
        __syncthreads();
        const unsigned ab = sb + (c8 & 1) * QSTG;
#pragma unroll
        for (int ks = 0; ks < 4; ks++) {
            const int kb = ks * 32;
            unsigned a0[4], a1[4];
            ldA(a0, ab, 144, m0,      kb, lane);
            ldA(a1, ab, 144, m0 + 16, kb, lane);
#pragma unroll
            for (int g = 0; g < 6; g++) {
                unsigned bf[4];
                ldB(bf, ab + 18432, 144, n0 + g * 16, kb, lane);
                mma_fp16(acc[0][2*g],   a0, bf[0], bf[1]);
                mma_fp16(acc[0][2*g+1], a0, bf[2], bf[3]);
                mma_fp16(acc[1][2*g],   a1, bf[0], bf[1]);
                mma_fp16(acc[1][2*g+1], a1, bf[2], bf[3]);
            }
        }
        __syncthreads();
    }

    // writeout: q,k direct; v staged transposed in stage-0 region (free)
#pragma unroll
    for (int mt = 0; mt < 2; mt++) {
#pragma unroll
        for (int half = 0; half < 2; half++) {
            int tl = m0 + mt * 16 + half * 8 + (lane >> 2);   // local row 0..127
            int r = row0 + tl;
            int b = r >> 11, s = r & (SLEN - 1);
#pragma unroll
            for (int nt = 0; nt < 12; nt++) {
                int col = n0 + nt * 8 + (lane & 3) * 2;
                int j = col >> 6, cc = col & 63;
                float v0 = acc[mt][nt][half * 2 + 0];
                float v1 = acc[mt][nt][half * 2 + 1];
                if (j == 0) { v0 *= 0.125f; v1 *= 0.125f; }
                if (j < 2) {
                    unsigned short* dst = (j == 0) ? g_qf : g_kf;
                    size_t base = ((size_t)(b * HNUM + h) * SLEN + s) * KDIM + cc;
                    *(unsigned*)(dst + base) = pk2(f2h(v0), f2h(v1));
                } else {   // V: [d][t] into stage 0
                    *(unsigned short*)(smc + (cc    ) * 272 + tl * 2) = f2h(v0);
                    *(unsigned short*)(smc + (cc + 1) * 272 + tl * 2) = f2h(v1);
                }
            }
        }
    }
    __syncthreads();
    {
        const int b = row0 >> 11, s0 = row0 & (SLEN - 1);
        const size_t vbase = ((size_t)(b * HNUM + h) * KDIM) * SLEN;
#pragma unroll
        for (int t = 0; t < 4; t++) {
            int idx = tid + t * 256, d = idx >> 4, q = idx & 15;
            *(uint4*)(g_vtf + vbase + (size_t)d * SLEN + s0 + q * 8) =
                *(const uint4*)(smc + d * 272 + q * 16);
        }
    }
}

// ================= attention (fp16; 8 warps as 4m x 2n; hoisted Q frags) =================
// grid (16, 32), block 256. Warp (wm,wn): q-rows 32wm..+31, key half 64wn..+63.
// smem: Q 0 (18432); stage s at 18432 + s*35840: K +0 (18432), V +18432 (17408).
// End: O/l partial exchange overlays dead stage-0 (128x68 fp32 + 128 fp32).
#define ASTG0 18432
#define ASTG  35840
#define ATT_SMEM (ASTG0 + 2 * ASTG)   // 90112
__global__ __launch_bounds__(256, 1) void attn_mma() {
    extern __shared__ char smc[];
    const unsigned sb = smem_u32(smc);
    const int tid = threadIdx.x, wid = tid >> 5, lane = tid & 31;
    const int wm = wid >> 1, wn = wid & 1;
    const int m0 = wm * 32, nh = wn * 64;
    const int bh = blockIdx.y, q0 = blockIdx.x * 128;
    const int b = bh >> 3, h = bh & 7;

    const size_t kbase = (size_t)bh * SLEN * KDIM;
    const size_t vbase = (size_t)bh * KDIM * SLEN;

    auto issue_kv = [&](int it) {
        const unsigned stb = sb + ASTG0 + (it & 1) * ASTG;
        const int t0 = it * 128;
#pragma unroll
        for (int t = 0; t < 4; t++) {                 // K tile [t][d]
            int idx = tid + t * 256, r = idx >> 3, q = idx & 7;
            CP16(stb + r * 144 + q * 16, g_kf + kbase + (size_t)(t0 + r) * KDIM + q * 8);
        }
#pragma unroll
        for (int t = 0; t < 4; t++) {                 // Vt tile [d][t]
            int idx = tid + t * 256, d = idx >> 4, q = idx & 15;
            CP16(stb + 18432 + d * 272 + q * 16, g_vtf + vbase + (size_t)d * SLEN + t0 + q * 8);
        }
    };

    // prologue: Q + stage 0, then hoist Q fragments into registers
    {
        const size_t qb = ((size_t)bh * SLEN + q0) * KDIM;
#pragma unroll
        for (int t = 0; t < 4; t++) {
            int idx = tid + t * 256, r = idx >> 3, q = idx & 7;
            CP16(sb + r * 144 + q * 16, g_qf + qb + (size_t)r * KDIM + q * 8);
        }
        issue_kv(0); CPCOMMIT();
    }
    CPWAIT0();
    __syncthreads();

    unsigned aq[4][2][4];          // [ks][mt][frag] — Q is loop-invariant
#pragma unroll
    for (int ks = 0; ks < 4; ks++) {
        ldA(aq[ks][0], sb, 144, m0,      ks * 32, lane);
        ldA(aq[ks][1], sb, 144, m0 + 16, ks * 32, lane);
    }

    float oacc[2][8][4];
    float lsum[2][2];
#pragma unroll
    for (int mt = 0; mt < 2; mt++) {
        lsum[mt][0] = lsum[mt][1] = 0.f;
#pragma unroll
        for (int n = 0; n < 8; n++)
#pragma unroll
            for (int c = 0; c < 4; c++) oacc[mt][n][c] = 0.f;
    }

    for (int it = 0; it < 16; it++) {
        if (it < 15) { issue_kv(it + 1); CPCOMMIT(); CPWAIT1(); } else { CPWAIT0(); }
        __syncthreads();
        const unsigned stb = sb + ASTG0 + (it & 1) * ASTG;

        // ---- S = Q K^T over this warp's 64-key half (ldB shared by 2 m-tiles) ----
        float sacc[2][8][4];
#pragma unroll
        for (int mt = 0; mt < 2; mt++)
#pragma unroll
            for (int n = 0; n < 8; n++)
#pragma unroll
                for (int c = 0; c < 4; c++) sacc[mt][n][c] = 0.f;
#pragma unroll
        for (int ks = 0; ks < 4; ks++) {
            const int kb = ks * 32;
#pragma unroll
            for (int g = 0; g < 4; g++) {
                unsigned bk[4];
                ldB(bk, stb, 144, nh + g * 16, kb, lane);
                mma_fp16(sacc[0][2*g],   aq[ks][0], bk[0], bk[1]);
                mma_fp16(sacc[0][2*g+1], aq[ks][0], bk[2], bk[3]);
                mma_fp16(sacc[1][2*g],   aq[ks][1], bk[0], bk[1]);
                mma_fp16(sacc[1][2*g+1], aq[ks][1], bk[2], bk[3]);
            }
        }

        // ---- p = exp(s); pack P as fp16 A-fragments; rowsum of ROUNDED p ----
        unsigned ph[2][4][4];
#pragma unroll
        for (int mt = 0; mt < 2; mt++)
#pragma unroll
            for (int nt = 0; nt < 8; nt++) {
                float p0 = __expf(sacc[mt][nt][0]);
                float p1 = __expf(sacc[mt][nt][1]);
                float p2 = __expf(sacc[mt][nt][2]);
                float p3 = __expf(sacc[mt][nt][3]);
                __half2 ha = __floats2half2_rn(p0, p1);
                __half2 hb = __floats2half2_rn(p2, p3);
                float2 fa = __half22float2(ha);
                float2 fb = __half22float2(hb);
                lsum[mt][0] += fa.x + fa.y;
                lsum[mt][1] += fb.x + fb.y;
                int kc = nt >> 1, o = (nt & 1) * 2;
                ph[mt][kc][o]     = *(unsigned*)&ha;
                ph[mt][kc][o + 1] = *(unsigned*)&hb;
            }

        // ---- O += P V over this warp's key half (ldB shared by 2 m-tiles) ----
#pragma unroll
        for (int kc = 0; kc < 4; kc++) {
            const int kb = nh * 2 + kc * 32;
#pragma unroll
            for (int g = 0; g < 4; g++) {
                unsigned bf[4];
                ldB(bf, stb + 18432, 272, g * 16, kb, lane);
                mma_fp16(oacc[0][2*g],   ph[0][kc], bf[0], bf[1]);
                mma_fp16(oacc[0][2*g+1], ph[0][kc], bf[2], bf[3]);
                mma_fp16(oacc[1][2*g],   ph[1][kc], bf[0], bf[1]);
                mma_fp16(oacc[1][2*g+1], ph[1][kc], bf[2], bf[3]);
            }
        }
        __syncthreads();
    }

    // ---- rowsum quad-reduce ----
#pragma unroll
    for (int mt = 0; mt < 2; mt++)
#pragma unroll
        for (int hf = 0; hf < 2; hf++) {
            float v = lsum[mt][hf];
            v += __shfl_xor_sync(0xffffffffu, v, 1);
            v += __shfl_xor_sync(0xffffffffu, v, 2);
            lsum[mt][hf] = v;
        }

    // ---- combine key-half partials via dead stage-0 region ----
    float* ox = (float*)(smc + ASTG0);                  // [128][68] fp32
    float* lx = (float*)(smc + ASTG0 + 34816);          // [128]
    const int rq = lane >> 2;
    if (wn == 1) {
#pragma unroll
        for (int mt = 0; mt < 2; mt++) {
            int r = m0 + mt * 16 + rq;
#pragma unroll
            for (int nt = 0; nt < 8; nt++) {
                int col = nt * 8 + (lane & 3) * 2;
                ox[(r    ) * 68 + col]     = oacc[mt][nt][0];
                ox[(r    ) * 68 + col + 1] = oacc[mt][nt][1];
                ox[(r + 8) * 68 + col]     = oacc[mt][nt][2];
                ox[(r + 8) * 68 + col + 1] = oacc[mt][nt][3];
            }
            if ((lane & 3) == 0) { lx[r] = lsum[mt][0]; lx[r + 8] = lsum[mt][1]; }
        }
    }
    __syncthreads();
    if (wn == 0) {
#pragma unroll
        for (int mt = 0; mt < 2; mt++) {
            int r = m0 + mt * 16 + rq;
            const float inv0 = 1.f / (lsum[mt][0] + lx[r]);
            const float inv1 = 1.f / (lsum[mt][1] + lx[r + 8]);
            const size_t base0 = ((size_t)b * SLEN + q0 + r) * DMODEL + h * KDIM;
            const size_t base1 = base0 + 8 * DMODEL;
#pragma unroll
            for (int nt = 0; nt < 8; nt++) {
                int col = nt * 8 + (lane & 3) * 2;
                float v0 = (oacc[mt][nt][0] + ox[(r    ) * 68 + col])     * inv0;
                float v1 = (oacc[mt][nt][1] + ox[(r    ) * 68 + col + 1]) * inv0;
                float v2 = (oacc[mt][nt][2] + ox[(r + 8) * 68 + col])     * inv1;
                float v3 = (oacc[mt][nt][3] + ox[(r + 8) * 68 + col + 1]) * inv1;
                *(unsigned*)(g_cf + base0 + col) = pk2(f2h(v0), f2h(v1));
                *(unsigned*)(g_cf + base1 + col) = pk2(f2h(v2), f2h(v3));
            }
        }
    }
}

// ================= output projection (R10 config: fp16 1-pass, 256 thr) =================
// grid (64, 4), block 256. 8 warps as 4m x 2n: warp tile 32 x 64.
// stage: A 0 (18432), B 18432 (18432)
#define OSTG 36864
#define OUT_SMEM (2 * OSTG)     // 73728
__global__ __launch_bounds__(256, 1) void outproj_mma(float* __restrict__ out) {
    extern __shared__ char smc[];
    const unsigned sb = smem_u32(smc);
    const int tid = threadIdx.x, wid = tid >> 5, lane = tid & 31;
    const int wm = wid >> 1, wn = wid & 1;
    const int row0 = blockIdx.x * 128, n0 = blockIdx.y * 128;

    auto issue = [&](int c8) {
        const unsigned ob = sb + (c8 & 1) * OSTG;
        const int e0 = c8 * 64;
#pragma unroll
        for (int t = 0; t < 4; t++) {
            int idx = tid + t * 256, r = idx >> 3, q = idx & 7;
            CP16(ob + r * 144 + q * 16, g_cf + (size_t)(row0 + r) * 512 + e0 + q * 8);
            CP16(ob + 18432 + r * 144 + q * 16, g_hktf + (size_t)(n0 + r) * 512 + e0 + q * 8);
        }
    };

    float acc[2][8][4];
#pragma unroll
    for (int a = 0; a < 2; a++)
#pragma unroll
        for (int n = 0; n < 8; n++)
#pragma unroll
            for (int c = 0; c < 4; c++) acc[a][n][c] = 0.f;

    issue(0); CPCOMMIT();
    for (int c8 = 0; c8 < 8; c8++) {
        if (c8 < 7) { issue(c8 + 1); CPCOMMIT(); CPWAIT1(); } else { CPWAIT0(); }
        __syncthreads();
        const unsigned ob = sb + (c8 & 1) * OSTG;
#pragma unroll
        for (int ks = 0; ks < 4; ks++) {
            const int kb = ks * 32;
            unsigned a0[4], a1[4];
            ldA(a0, ob, 144, wm * 32,      kb, lane);
            ldA(a1, ob, 144, wm * 32 + 16, kb, lane);
#pragma unroll
            for (int g = 0; g < 4; g++) {
                unsigned bf[4];
                ldB(bf, ob + 18432, 144, wn * 64 + g * 16, kb, lane);
                mma_fp16(acc[0][2*g],   a0, bf[0], bf[1]);
                mma_fp16(acc[0][2*g+1], a0, bf[2], bf[3]);
                mma_fp16(acc[1][2*g],   a1, bf[0], bf[1]);
                mma_fp16(acc[1][2*g+1], a1, bf[2], bf[3]);
            }
        }
        __syncthreads();
    }

#pragma unroll
    for (int mt = 0; mt < 2; mt++) {
        int r0 = row0 + wm * 32 + mt * 16 + (lane >> 2);
#pragma unroll
        for (int hf = 0; hf < 2; hf++) {
            size_t base = (size_t)(r0 + hf * 8) * DMODEL + n0;
#pragma unroll
            for (int nt = 0; nt < 8; nt++) {
                int col = wn * 64 + nt * 8 + (lane & 3) * 2;
                out[base + col]     = acc[mt][nt][hf * 2 + 0];
                out[base + col + 1] = acc[mt][nt][hf * 2 + 1];
            }
        }
    }
}

// =====================================================================
extern "C" void kernel_launch(void* const* d_in, const int* in_sizes, int n_in,
                              void* d_out, int out_size)
{
    const float* x    = (const float*)d_in[0];   // (4, 2048, 512)
    const float* kern = (const float*)d_in[1];   // (24, 512, 64)
    const float* hk   = (const float*)d_in[2];   // (512, 512)
    float* out = (float*)d_out;                  // (4, 2048, 512)

    cudaFuncSetAttribute(qkv_mma,     cudaFuncAttributeMaxDynamicSharedMemorySize, QKV_SMEM);
    cudaFuncSetAttribute(attn_mma,    cudaFuncAttributeMaxDynamicSharedMemorySize, ATT_SMEM);
    cudaFuncSetAttribute(outproj_mma, cudaFuncAttributeMaxDynamicSharedMemorySize, OUT_SMEM);

    const int n4x = BSROWS * DMODEL / 4;                     // 1048576
    convert_x<<<(n4x + 255) / 256, 256>>>(x, n4x);
    transpose_w<<<(24 * 64 * 64 + 255) / 256, 256>>>(kern, 24 * 64 * 64);
    transpose_hk<<<(64 * 512 + 255) / 256, 256>>>(hk, 64 * 512);

    qkv_mma<<<dim3(BSROWS / 128, HNUM), 256, QKV_SMEM>>>();
    attn_mma<<<dim3(SLEN / 128, NBH), 256, ATT_SMEM>>>();
    outproj_mma<<<dim3(BSROWS / 128, DMODEL / 128), 256, OUT_SMEM>>>(out);
}

// round 14
// speedup vs baseline: 1.1503x; 1.0616x over previous
#include <cuda_runtime.h>
#include <cuda_fp16.h>

#define BDIM   4
#define SLEN   2048
#define DMODEL 512
#define HNUM   8
#define KDIM   64
#define BSROWS (BDIM * SLEN)   // 8192
#define NBH    (BDIM * HNUM)   // 32

// Q pre-scale: 1/sqrt(64) * log2(e)  (S comes out in log2 domain for ex2)
#define QSCALE 0.18033688011112042f

// ---------------- scratch (static device globals, all fp16-as-ushort) ----------------
__device__ __align__(16) unsigned short g_xf[BSROWS * DMODEL];          // x
__device__ __align__(16) unsigned short g_wtf[24 * KDIM * DMODEL];      // [hj][n][d]
__device__ __align__(16) unsigned short g_hktf[DMODEL * DMODEL];        // [n][e]
__device__ __align__(16) unsigned short g_qf[NBH * SLEN * KDIM];        // [bh][s][d] (pre-scaled)
__device__ __align__(16) unsigned short g_kf[NBH * SLEN * KDIM];        // [bh][t][d]
__device__ __align__(16) unsigned short g_vtf[NBH * KDIM * SLEN];       // [bh][d][t]
__device__ __align__(16) unsigned short g_cf[BSROWS * DMODEL];          // concat [row][e]

// ---------------- helpers ----------------
__device__ __forceinline__ unsigned smem_u32(const void* p) {
    unsigned a;
    asm("{ .reg .u64 t; cvta.to.shared.u64 t, %1; cvt.u32.u64 %0, t; }" : "=r"(a) : "l"(p));
    return a;
}
#define CP16(dst, src) \
    asm volatile("cp.async.cg.shared.global [%0], [%1], 16;" :: "r"(dst), "l"(src))
#define CPCOMMIT() asm volatile("cp.async.commit_group;" ::: "memory")
#define CPWAIT0()  asm volatile("cp.async.wait_group 0;" ::: "memory")
#define CPWAIT1()  asm volatile("cp.async.wait_group 1;" ::: "memory")
#define CPWAIT2()  asm volatile("cp.async.wait_group 2;" ::: "memory")

__device__ __forceinline__ void ldsm4(unsigned* r, unsigned a) {
    asm volatile("ldmatrix.sync.aligned.m8n8.x4.shared.b16 {%0,%1,%2,%3}, [%4];"
        : "=r"(r[0]), "=r"(r[1]), "=r"(r[2]), "=r"(r[3]) : "r"(a));
}
// A operand m16 x k16 at (m0, kbyte), row-major smem, stride bytes
__device__ __forceinline__ void ldA(unsigned* r, unsigned base, int stride, int m0, int kb, int lane) {
    int row = m0 + (lane & 7) + ((lane >> 3) & 1) * 8;
    int col = kb + (lane >> 4) * 16;
    ldsm4(r, base + row * stride + col);
}
// B operand: two n8 tiles (n0, n0+8) x k16 at kbyte
__device__ __forceinline__ void ldB(unsigned* r, unsigned base, int stride, int n0, int kb, int lane) {
    int row = n0 + (lane & 7) + (lane >> 4) * 8;
    int col = kb + ((lane >> 3) & 1) * 16;
    ldsm4(r, base + row * stride + col);
}
__device__ __forceinline__ void mma_fp16(float* c, const unsigned* a, unsigned b0, unsigned b1) {
    asm volatile("mma.sync.aligned.m16n8k16.row.col.f32.f16.f16.f32 "
        "{%0,%1,%2,%3}, {%4,%5,%6,%7}, {%8,%9}, {%0,%1,%2,%3};"
        : "+f"(c[0]), "+f"(c[1]), "+f"(c[2]), "+f"(c[3])
        : "r"(a[0]), "r"(a[1]), "r"(a[2]), "r"(a[3]), "r"(b0), "r"(b1));
}
__device__ __forceinline__ unsigned h2ex2(unsigned x) {
    unsigned r;
    asm("ex2.approx.f16x2 %0, %1;" : "=r"(r) : "r"(x));
    return r;
}
__device__ __forceinline__ unsigned short f2h(float x) {
    __half v = __float2half_rn(x);
    return *(unsigned short*)&v;
}
__device__ __forceinline__ unsigned pk2(unsigned short a, unsigned short b) {
    return (unsigned)a | ((unsigned)b << 16);
}

// ================= convert kernels =================
__global__ void convert_x(const float* __restrict__ src, int n4) {
    int i = blockIdx.x * blockDim.x + threadIdx.x;
    if (i >= n4) return;
    float4 v = ((const float4*)src)[i];
    ((uint2*)g_xf)[i] = make_uint2(pk2(f2h(v.x), f2h(v.y)), pk2(f2h(v.z), f2h(v.w)));
}
// w: [24][512][64] -> [24][64][512] fp16
__global__ void transpose_w(const float* __restrict__ src, int nwork) {
    int i = blockIdx.x * blockDim.x + threadIdx.x;
    if (i >= nwork) return;
    int n = i % 64, rest = i / 64;
    int d8 = rest & 63, mat = rest >> 6;
    int d0 = d8 * 8;
    unsigned short h[8];
#pragma unroll
    for (int j = 0; j < 8; j++)
        h[j] = f2h(src[(size_t)mat * 512 * 64 + (size_t)(d0 + j) * 64 + n]);
    size_t dst = (size_t)mat * 64 * 512 + (size_t)n * 512 + d0;
    *(uint4*)(g_wtf + dst) = make_uint4(pk2(h[0],h[1]), pk2(h[2],h[3]), pk2(h[4],h[5]), pk2(h[6],h[7]));
}
// hk: [512][512] -> transposed fp16
__global__ void transpose_hk(const float* __restrict__ src, int nwork) {
    int i = blockIdx.x * blockDim.x + threadIdx.x;
    if (i >= nwork) return;
    int n = i % 512, d8 = i / 512;
    int d0 = d8 * 8;
    unsigned short h[8];
#pragma unroll
    for (int j = 0; j < 8; j++)
        h[j] = f2h(src[(size_t)(d0 + j) * 512 + n]);
    size_t dst = (size_t)n * 512 + d0;
    *(uint4*)(g_hktf + dst) = make_uint4(pk2(h[0],h[1]), pk2(h[2],h[3]), pk2(h[4],h[5]), pk2(h[6],h[7]));
}

// ================= QKV projection (fp16 1-pass, 256 thr, 3-stage) =================
// grid (64, 8), block 256. 8 warps as 4m x 2n: warp tile 32 x 96.
// stage (46080 B): A 0 (18432 = 128x144), B 18432 (27648 = 192x144). 3 buffers.
#define QSTG 46080
#define QKV_SMEM (3 * QSTG)     // 138240
__global__ __launch_bounds__(256, 1) void qkv_mma() {
    extern __shared__ char smc[];
    const unsigned sb = smem_u32(smc);
    const int tid = threadIdx.x, wid = tid >> 5, lane = tid & 31;
    const int wm = wid >> 1, wn = wid & 1;
    const int h = blockIdx.y, row0 = blockIdx.x * 128;
    const int m0 = wm * 32, n0 = wn * 96;

    auto issue = [&](int c8) {
        const unsigned ab = sb + (c8 % 3) * QSTG;
        const int d0 = c8 * 64;
#pragma unroll
        for (int t = 0; t < 4; t++) {               // A: 128 rows x 8 x 16B
            int idx = tid + t * 256, r = idx >> 3, q = idx & 7;
            CP16(ab + r * 144 + q * 16, g_xf + (size_t)(row0 + r) * 512 + d0 + q * 8);
        }
#pragma unroll
        for (int t = 0; t < 6; t++) {               // B: 192 rows
            int idx = tid + t * 256, r = idx >> 3, q = idx & 7;
            CP16(ab + 18432 + r * 144 + q * 16, g_wtf + (size_t)(h * 192 + r) * 512 + d0 + q * 8);
        }
    };

    float acc[2][12][4];
#pragma unroll
    for (int a = 0; a < 2; a++)
#pragma unroll
        for (int n = 0; n < 12; n++)
#pragma unroll
            for (int c = 0; c < 4; c++) acc[a][n][c] = 0.f;

    issue(0); CPCOMMIT();
    issue(1); CPCOMMIT();
    for (int c8 = 0; c8 < 8; c8++) {
        if (c8 < 7) CPWAIT1(); else CPWAIT0();
        __syncthreads();
        if (c8 < 6) { issue(c8 + 2); CPCOMMIT(); }
        const unsigned ab = sb + (c8 % 3) * QSTG;
#pragma unroll
        for (int ks = 0; ks < 4; ks++) {
            const int kb = ks * 32;
            unsigned a0[4], a1[4];
            ldA(a0, ab, 144, m0,      kb, lane);
            ldA(a1, ab, 144, m0 + 16, kb, lane);
#pragma unroll
            for (int g = 0; g < 6; g++) {
                unsigned bf[4];
                ldB(bf, ab + 18432, 144, n0 + g * 16, kb, lane);
                mma_fp16(acc[0][2*g],   a0, bf[0], bf[1]);
                mma_fp16(acc[0][2*g+1], a0, bf[2], bf[3]);
                mma_fp16(acc[1][2*g],   a1, bf[0], bf[1]);
                mma_fp16(acc[1][2*g+1], a1, bf[2], bf[3]);
            }
        }
    }

    // writeout: q,k direct; v staged transposed in buffer-2 region (dead:
    // last stages used buffers 0 (c8=6) and 1 (c8=7); all warps passed
    // the top-of-7 sync, so buffer 2 (stage 5) is free).
    char* vst = smc + 2 * QSTG;
#pragma unroll
    for (int mt = 0; mt < 2; mt++) {
#pragma unroll
        for (int half = 0; half < 2; half++) {
            int tl = m0 + mt * 16 + half * 8 + (lane >> 2);   // local row 0..127
            int r = row0 + tl;
            int b = r >> 11, s = r & (SLEN - 1);
#pragma unroll
            for (int nt = 0; nt < 12; nt++) {
                int col = n0 + nt * 8 + (lane & 3) * 2;
                int j = col >> 6, cc = col & 63;
                float v0 = acc[mt][nt][half * 2 + 0];
                float v1 = acc[mt][nt][half * 2 + 1];
                if (j == 0) { v0 *= QSCALE; v1 *= QSCALE; }
                if (j < 2) {
                    unsigned short* dst = (j == 0) ? g_qf : g_kf;
                    size_t base = ((size_t)(b * HNUM + h) * SLEN + s) * KDIM + cc;
                    *(unsigned*)(dst + base) = pk2(f2h(v0), f2h(v1));
                } else {   // V: [d][t] into staging
                    *(unsigned short*)(vst + (cc    ) * 272 + tl * 2) = f2h(v0);
                    *(unsigned short*)(vst + (cc + 1) * 272 + tl * 2) = f2h(v1);
                }
            }
        }
    }
    __syncthreads();
    {
        const int b = row0 >> 11, s0 = row0 & (SLEN - 1);
        const size_t vbase = ((size_t)(b * HNUM + h) * KDIM) * SLEN;
#pragma unroll
        for (int t = 0; t < 4; t++) {
            int idx = tid + t * 256, d = idx >> 4, q = idx & 15;
            *(uint4*)(g_vtf + vbase + (size_t)d * SLEN + s0 + q * 8) =
                *(const uint4*)(vst + d * 272 + q * 16);
        }
    }
}

// ================= attention (fp16; 4m x 2n warps; ex2.f16x2; 3-stage) =================
// grid (16, 32), block 256. Warp (wm,wn): q-rows 32wm..+31, key half 64wn..+63.
// smem: Q 0 (18432); stage s (s=0..2) at 18432 + s*35840: K +0 (18432), V +18432 (17408).
// End: O/l partial exchange overlays buffer 1 (dead: last compute used buffer 0).
#define ASTG0 18432
#define ASTG  35840
#define ATT_SMEM (ASTG0 + 3 * ASTG)   // 125952
__global__ __launch_bounds__(256, 1) void attn_mma() {
    extern __shared__ char smc[];
    const unsigned sb = smem_u32(smc);
    const int tid = threadIdx.x, wid = tid >> 5, lane = tid & 31;
    const int wm = wid >> 1, wn = wid & 1;
    const int m0 = wm * 32, nh = wn * 64;
    const int bh = blockIdx.y, q0 = blockIdx.x * 128;
    const int b = bh >> 3, h = bh & 7;

    const size_t kbase = (size_t)bh * SLEN * KDIM;
    const size_t vbase = (size_t)bh * KDIM * SLEN;

    auto issue_kv = [&](int it) {
        const unsigned stb = sb + ASTG0 + (it % 3) * ASTG;
        const int t0 = it * 128;
#pragma unroll
        for (int t = 0; t < 4; t++) {                 // K tile [t][d]
            int idx = tid + t * 256, r = idx >> 3, q = idx & 7;
            CP16(stb + r * 144 + q * 16, g_kf + kbase + (size_t)(t0 + r) * KDIM + q * 8);
        }
#pragma unroll
        for (int t = 0; t < 4; t++) {                 // Vt tile [d][t]
            int idx = tid + t * 256, d = idx >> 4, q = idx & 15;
            CP16(stb + 18432 + d * 272 + q * 16, g_vtf + vbase + (size_t)d * SLEN + t0 + q * 8);
        }
    };

    // prologue: Q (own group), then kv0, kv1
    {
        const size_t qb = ((size_t)bh * SLEN + q0) * KDIM;
#pragma unroll
        for (int t = 0; t < 4; t++) {
            int idx = tid + t * 256, r = idx >> 3, q = idx & 7;
            CP16(sb + r * 144 + q * 16, g_qf + qb + (size_t)r * KDIM + q * 8);
        }
        CPCOMMIT();
        issue_kv(0); CPCOMMIT();
        issue_kv(1); CPCOMMIT();
    }
    CPWAIT2();           // Q group done
    __syncthreads();

    unsigned aq[4][2][4];          // [ks][mt][frag] — Q is loop-invariant
#pragma unroll
    for (int ks = 0; ks < 4; ks++) {
        ldA(aq[ks][0], sb, 144, m0,      ks * 32, lane);
        ldA(aq[ks][1], sb, 144, m0 + 16, ks * 32, lane);
    }

    float oacc[2][8][4];
    float lsum[2][2];
#pragma unroll
    for (int mt = 0; mt < 2; mt++) {
        lsum[mt][0] = lsum[mt][1] = 0.f;
#pragma unroll
        for (int n = 0; n < 8; n++)
#pragma unroll
            for (int c = 0; c < 4; c++) oacc[mt][n][c] = 0.f;
    }

    for (int it = 0; it < 16; it++) {
        if (it < 15) CPWAIT1(); else CPWAIT0();
        __syncthreads();
        if (it < 14) { issue_kv(it + 2); CPCOMMIT(); }
        const unsigned stb = sb + ASTG0 + (it % 3) * ASTG;

        // ---- S = Q K^T over this warp's 64-key half (log2 domain) ----
        float sacc[2][8][4];
#pragma unroll
        for (int mt = 0; mt < 2; mt++)
#pragma unroll
            for (int n = 0; n < 8; n++)
#pragma unroll
                for (int c = 0; c < 4; c++) sacc[mt][n][c] = 0.f;
#pragma unroll
        for (int ks = 0; ks < 4; ks++) {
            const int kb = ks * 32;
#pragma unroll
            for (int g = 0; g < 4; g++) {
                unsigned bk[4];
                ldB(bk, stb, 144, nh + g * 16, kb, lane);
                mma_fp16(sacc[0][2*g],   aq[ks][0], bk[0], bk[1]);
                mma_fp16(sacc[0][2*g+1], aq[ks][0], bk[2], bk[3]);
                mma_fp16(sacc[1][2*g],   aq[ks][1], bk[0], bk[1]);
                mma_fp16(sacc[1][2*g+1], aq[ks][1], bk[2], bk[3]);
            }
        }

        // ---- per-k16-chunk: p = 2^s via ex2.f16x2, then its PV MMAs ----
#pragma unroll
        for (int kc = 0; kc < 4; kc++) {
            unsigned ph[2][4];
#pragma unroll
            for (int mt = 0; mt < 2; mt++)
#pragma unroll
                for (int j = 0; j < 2; j++) {
                    const int nt = kc * 2 + j;
                    __half2 ha = __floats2half2_rn(sacc[mt][nt][0], sacc[mt][nt][1]);
                    __half2 hb = __floats2half2_rn(sacc[mt][nt][2], sacc[mt][nt][3]);
                    unsigned pa = h2ex2(*(unsigned*)&ha);
                    unsigned pb = h2ex2(*(unsigned*)&hb);
                    float2 fa = __half22float2(*(__half2*)&pa);
                    float2 fb = __half22float2(*(__half2*)&pb);
                    lsum[mt][0] += fa.x + fa.y;
                    lsum[mt][1] += fb.x + fb.y;
                    ph[mt][j * 2]     = pa;
                    ph[mt][j * 2 + 1] = pb;
                }
            const int kb = nh * 2 + kc * 32;
#pragma unroll
            for (int g = 0; g < 4; g++) {
                unsigned bf[4];
                ldB(bf, stb + 18432, 272, g * 16, kb, lane);
                mma_fp16(oacc[0][2*g],   ph[0], bf[0], bf[1]);
                mma_fp16(oacc[0][2*g+1], ph[0], bf[2], bf[3]);
                mma_fp16(oacc[1][2*g],   ph[1], bf[0], bf[1]);
                mma_fp16(oacc[1][2*g+1], ph[1], bf[2], bf[3]);
            }
        }
    }

    // ---- rowsum quad-reduce ----
#pragma unroll
    for (int mt = 0; mt < 2; mt++)
#pragma unroll
        for (int hf = 0; hf < 2; hf++) {
            float v = lsum[mt][hf];
            v += __shfl_xor_sync(0xffffffffu, v, 1);
            v += __shfl_xor_sync(0xffffffffu, v, 2);
            lsum[mt][hf] = v;
        }

    // ---- combine key-half partials via buffer-1 region (dead: last compute
    //      used buffer 0 (it=15); all warps passed the top-of-15 sync, so
    //      buffer 1 (stage 13) is free) ----
    float* ox = (float*)(smc + ASTG0 + ASTG);           // [128][68] fp32
    float* lx = (float*)(smc + ASTG0 + ASTG + 34816);   // [128]
    const int rq = lane >> 2;
    if (wn == 1) {
#pragma unroll
        for (int mt = 0; mt < 2; mt++) {
            int r = m0 + mt * 16 + rq;
#pragma unroll
            for (int nt = 0; nt < 8; nt++) {
                int col = nt * 8 + (lane & 3) * 2;
                ox[(r    ) * 68 + col]     = oacc[mt][nt][0];
                ox[(r    ) * 68 + col + 1] = oacc[mt][nt][1];
                ox[(r + 8) * 68 + col]     = oacc[mt][nt][2];
                ox[(r + 8) * 68 + col + 1] = oacc[mt][nt][3];
            }
            if ((lane & 3) == 0) { lx[r] = lsum[mt][0]; lx[r + 8] = lsum[mt][1]; }
        }
    }
    __syncthreads();
    if (wn == 0) {
#pragma unroll
        for (int mt = 0; mt < 2; mt++) {
            int r = m0 + mt * 16 + rq;
            const float inv0 = 1.f / (lsum[mt][0] + lx[r]);
            const float inv1 = 1.f / (lsum[mt][1] + lx[r + 8]);
            const size_t base0 = ((size_t)b * SLEN + q0 + r) * DMODEL + h * KDIM;
            const size_t base1 = base0 + 8 * DMODEL;
#pragma unroll
            for (int nt = 0; nt < 8; nt++) {
                int col = nt * 8 + (lane & 3) * 2;
                float v0 = (oacc[mt][nt][0] + ox[(r    ) * 68 + col])     * inv0;
                float v1 = (oacc[mt][nt][1] + ox[(r    ) * 68 + col + 1]) * inv0;
                float v2 = (oacc[mt][nt][2] + ox[(r + 8) * 68 + col])     * inv1;
                float v3 = (oacc[mt][nt][3] + ox[(r + 8) * 68 + col + 1]) * inv1;
                *(unsigned*)(g_cf + base0 + col) = pk2(f2h(v0), f2h(v1));
                *(unsigned*)(g_cf + base1 + col) = pk2(f2h(v2), f2h(v3));
            }
        }
    }
}

// ================= output projection (fp16 1-pass, 256 thr, 3-stage) =================
// grid (64, 4), block 256. 8 warps as 4m x 2n: warp tile 32 x 64.
// stage: A 0 (18432), B 18432 (18432). 3 buffers.
#define OSTG 36864
#define OUT_SMEM (3 * OSTG)     // 110592
__global__ __launch_bounds__(256, 1) void outproj_mma(float* __restrict__ out) {
    extern __shared__ char smc[];
    const unsigned sb = smem_u32(smc);
    const int tid = threadIdx.x, wid = tid >> 5, lane = tid & 31;
    const int wm = wid >> 1, wn = wid & 1;
    const int row0 = blockIdx.x * 128, n0 = blockIdx.y * 128;

    auto issue = [&](int c8) {
        const unsigned ob = sb + (c8 % 3) * OSTG;
        const int e0 = c8 * 64;
#pragma unroll
        for (int t = 0; t < 4; t++) {
            int idx = tid + t * 256, r = idx >> 3, q = idx & 7;
            CP16(ob + r * 144 + q * 16, g_cf + (size_t)(row0 + r) * 512 + e0 + q * 8);
            CP16(ob + 18432 + r * 144 + q * 16, g_hktf + (size_t)(n0 + r) * 512 + e0 + q * 8);
        }
    };

    float acc[2][8][4];
#pragma unroll
    for (int a = 0; a < 2; a++)
#pragma unroll
        for (int n = 0; n < 8; n++)
#pragma unroll
            for (int c = 0; c < 4; c++) acc[a][n][c] = 0.f;

    issue(0); CPCOMMIT();
    issue(1); CPCOMMIT();
    for (int c8 = 0; c8 < 8; c8++) {
        if (c8 < 7) CPWAIT1(); else CPWAIT0();
        __syncthreads();
        if (c8 < 6) { issue(c8 + 2); CPCOMMIT(); }
        const unsigned ob = sb + (c8 % 3) * OSTG;
#pragma unroll
        for (int ks = 0; ks < 4; ks++) {
            const int kb = ks * 32;
            unsigned a0[4], a1[4];
            ldA(a0, ob, 144, wm * 32,      kb, lane);
            ldA(a1, ob, 144, wm * 32 + 16, kb, lane);
#pragma unroll
            for (int g = 0; g < 4; g++) {
                unsigned bf[4];
                ldB(bf, ob + 18432, 144, wn * 64 + g * 16, kb, lane);
                mma_fp16(acc[0][2*g],   a0, bf[0], bf[1]);
                mma_fp16(acc[0][2*g+1], a0, bf[2], bf[3]);
                mma_fp16(acc[1][2*g],   a1, bf[0], bf[1]);
                mma_fp16(acc[1][2*g+1], a1, bf[2], bf[3]);
            }
        }
    }

#pragma unroll
    for (int mt = 0; mt < 2; mt++) {
        int r0 = row0 + wm * 32 + mt * 16 + (lane >> 2);
#pragma unroll
        for (int hf = 0; hf < 2; hf++) {
            size_t base = (size_t)(r0 + hf * 8) * DMODEL + n0;
#pragma unroll
            for (int nt = 0; nt < 8; nt++) {
                int col = wn * 64 + nt * 8 + (lane & 3) * 2;
                out[base + col]     = acc[mt][nt][hf * 2 + 0];
                out[base + col + 1] = acc[mt][nt][hf * 2 + 1];
            }
        }
    }
}

// =====================================================================
extern "C" void kernel_launch(void* const* d_in, const int* in_sizes, int n_in,
                              void* d_out, int out_size)
{
    const float* x    = (const float*)d_in[0];   // (4, 2048, 512)
    const float* kern = (const float*)d_in[1];   // (24, 512, 64)
    const float* hk   = (const float*)d_in[2];   // (512, 512)
    float* out = (float*)d_out;                  // (4, 2048, 512)

    cudaFuncSetAttribute(qkv_mma,     cudaFuncAttributeMaxDynamicSharedMemorySize, QKV_SMEM);
    cudaFuncSetAttribute(attn_mma,    cudaFuncAttributeMaxDynamicSharedMemorySize, ATT_SMEM);
    cudaFuncSetAttribute(outproj_mma, cudaFuncAttributeMaxDynamicSharedMemorySize, OUT_SMEM);

    const int n4x = BSROWS * DMODEL / 4;                     // 1048576
    convert_x<<<(n4x + 255) / 256, 256>>>(x, n4x);
    transpose_w<<<(24 * 64 * 64 + 255) / 256, 256>>>(kern, 24 * 64 * 64);
    transpose_hk<<<(64 * 512 + 255) / 256, 256>>>(hk, 64 * 512);

    qkv_mma<<<dim3(BSROWS / 128, HNUM), 256, QKV_SMEM>>>();
    attn_mma<<<dim3(SLEN / 128, NBH), 256, ATT_SMEM>>>();
    outproj_mma<<<dim3(BSROWS / 128, DMODEL / 128), 256, OUT_SMEM>>>(out);
}

// round 16
// speedup vs baseline: 1.2152x; 1.0564x over previous
#include <cuda_runtime.h>
#include <cuda_fp16.h>

#define BDIM   4
#define SLEN   2048
#define DMODEL 512
#define HNUM   8
#define KDIM   64
#define BSROWS (BDIM * SLEN)   // 8192
#define NBH    (BDIM * HNUM)   // 32

// Q pre-scale: 1/sqrt(64) * log2(e)  (S comes out in log2 domain for ex2)
#define QSCALE 0.18033688011112042f

// ---------------- scratch (static device globals, all fp16-as-ushort) ----------------
__device__ __align__(16) unsigned short g_xf[BSROWS * DMODEL];          // x
__device__ __align__(16) unsigned short g_wtf[24 * KDIM * DMODEL];      // [hj][n][d]
__device__ __align__(16) unsigned short g_hktf[DMODEL * DMODEL];        // [n][e]
__device__ __align__(16) unsigned short g_qf[NBH * SLEN * KDIM];        // [bh][s][d] (pre-scaled)
__device__ __align__(16) unsigned short g_kf[NBH * SLEN * KDIM];        // [bh][t][d]
__device__ __align__(16) unsigned short g_vtf[NBH * KDIM * SLEN];       // [bh][d][t]
__device__ __align__(16) unsigned short g_cf[BSROWS * DMODEL];          // concat [row][e]

// ---------------- helpers ----------------
__device__ __forceinline__ unsigned smem_u32(const void* p) {
    unsigned a;
    asm("{ .reg .u64 t; cvta.to.shared.u64 t, %1; cvt.u32.u64 %0, t; }" : "=r"(a) : "l"(p));
    return a;
}
#define CP16(dst, src) \
    asm volatile("cp.async.cg.shared.global [%0], [%1], 16;" :: "r"(dst), "l"(src))
#define CPCOMMIT() asm volatile("cp.async.commit_group;" ::: "memory")
#define CPWAIT0()  asm volatile("cp.async.wait_group 0;" ::: "memory")
#define CPWAIT1()  asm volatile("cp.async.wait_group 1;" ::: "memory")
#define CPWAIT2()  asm volatile("cp.async.wait_group 2;" ::: "memory")

__device__ __forceinline__ void ldsm4(unsigned* r, unsigned a) {
    asm volatile("ldmatrix.sync.aligned.m8n8.x4.shared.b16 {%0,%1,%2,%3}, [%4];"
        : "=r"(r[0]), "=r"(r[1]), "=r"(r[2]), "=r"(r[3]) : "r"(a));
}
// A operand m16 x k16 at (m0, kbyte), row-major smem, stride bytes
__device__ __forceinline__ void ldA(unsigned* r, unsigned base, int stride, int m0, int kb, int lane) {
    int row = m0 + (lane & 7) + ((lane >> 3) & 1) * 8;
    int col = kb + (lane >> 4) * 16;
    ldsm4(r, base + row * stride + col);
}
// B operand: two n8 tiles (n0, n0+8) x k16 at kbyte
__device__ __forceinline__ void ldB(unsigned* r, unsigned base, int stride, int n0, int kb, int lane) {
    int row = n0 + (lane & 7) + (lane >> 4) * 8;
    int col = kb + ((lane >> 3) & 1) * 16;
    ldsm4(r, base + row * stride + col);
}
__device__ __forceinline__ void mma_fp16(float* c, const unsigned* a, unsigned b0, unsigned b1) {
    asm volatile("mma.sync.aligned.m16n8k16.row.col.f32.f16.f16.f32 "
        "{%0,%1,%2,%3}, {%4,%5,%6,%7}, {%8,%9}, {%0,%1,%2,%3};"
        : "+f"(c[0]), "+f"(c[1]), "+f"(c[2]), "+f"(c[3])
        : "r"(a[0]), "r"(a[1]), "r"(a[2]), "r"(a[3]), "r"(b0), "r"(b1));
}
// fp16 accumulator variant (D,C in packed half2 x2) — used ONLY for S (4-step chain)
__device__ __forceinline__ void mma_fp16h(unsigned* d, const unsigned* a, unsigned b0, unsigned b1) {
    asm volatile("mma.sync.aligned.m16n8k16.row.col.f16.f16.f16.f16 "
        "{%0,%1}, {%2,%3,%4,%5}, {%6,%7}, {%0,%1};"
        : "+r"(d[0]), "+r"(d[1])
        : "r"(a[0]), "r"(a[1]), "r"(a[2]), "r"(a[3]), "r"(b0), "r"(b1));
}
__device__ __forceinline__ unsigned h2ex2(unsigned x) {
    unsigned r;
    asm("ex2.approx.f16x2 %0, %1;" : "=r"(r) : "r"(x));
    return r;
}
__device__ __forceinline__ unsigned short f2h(float x) {
    __half v = __float2half_rn(x);
    return *(unsigned short*)&v;
}
__device__ __forceinline__ unsigned pk2(unsigned short a, unsigned short b) {
    return (unsigned)a | ((unsigned)b << 16);
}

// ================= merged convert kernel =================
// blocks [0, 4096): convert_x; [4096, 4480): transpose_w; [4480, 4608): transpose_hk
#define CVT_XB 4096
#define CVT_WB 384
#define CVT_HB 128
__global__ void convert_all(const float* __restrict__ x,
                            const float* __restrict__ w,
                            const float* __restrict__ hk) {
    const int bidx = blockIdx.x;
    if (bidx < CVT_XB) {
        int i = bidx * 256 + threadIdx.x;                 // n4 = 1048576 exactly
        float4 v = ((const float4*)x)[i];
        ((uint2*)g_xf)[i] = make_uint2(pk2(f2h(v.x), f2h(v.y)), pk2(f2h(v.z), f2h(v.w)));
    } else if (bidx < CVT_XB + CVT_WB) {
        int i = (bidx - CVT_XB) * 256 + threadIdx.x;      // nwork = 98304 exactly
        int n = i % 64, rest = i / 64;
        int d8 = rest & 63, mat = rest >> 6;
        int d0 = d8 * 8;
        unsigned short h[8];
#pragma unroll
        for (int j = 0; j < 8; j++)
            h[j] = f2h(w[(size_t)mat * 512 * 64 + (size_t)(d0 + j) * 64 + n]);
        size_t dst = (size_t)mat * 64 * 512 + (size_t)n * 512 + d0;
        *(uint4*)(g_wtf + dst) = make_uint4(pk2(h[0],h[1]), pk2(h[2],h[3]), pk2(h[4],h[5]), pk2(h[6],h[7]));
    } else {
        int i = (bidx - CVT_XB - CVT_WB) * 256 + threadIdx.x;   // nwork = 32768 exactly
        int n = i % 512, d8 = i / 512;
        int d0 = d8 * 8;
        unsigned short h[8];
#pragma unroll
        for (int j = 0; j < 8; j++)
            h[j] = f2h(hk[(size_t)(d0 + j) * 512 + n]);
        size_t dst = (size_t)n * 512 + d0;
        *(uint4*)(g_hktf + dst) = make_uint4(pk2(h[0],h[1]), pk2(h[2],h[3]), pk2(h[4],h[5]), pk2(h[6],h[7]));
    }
}

// ================= QKV projection (fp16 1-pass, 256 thr, 3-stage) =================
// grid (64, 8), block 256. 8 warps as 4m x 2n: warp tile 32 x 96.
// stage (46080 B): A 0 (18432 = 128x144), B 18432 (27648 = 192x144). 3 buffers.
#define QSTG 46080
#define QKV_SMEM (3 * QSTG)     // 138240
__global__ __launch_bounds__(256, 1) void qkv_mma() {
    extern __shared__ char smc[];
    const unsigned sb = smem_u32(smc);
    const int tid = threadIdx.x, wid = tid >> 5, lane = tid & 31;
    const int wm = wid >> 1, wn = wid & 1;
    const int h = blockIdx.y, row0 = blockIdx.x * 128;
    const int m0 = wm * 32, n0 = wn * 96;

    auto issue = [&](int c8) {
        const unsigned ab = sb + (c8 % 3) * QSTG;
        const int d0 = c8 * 64;
#pragma unroll
        for (int t = 0; t < 4; t++) {               // A: 128 rows x 8 x 16B
            int idx = tid + t * 256, r = idx >> 3, q = idx & 7;
            CP16(ab + r * 144 + q * 16, g_xf + (size_t)(row0 + r) * 512 + d0 + q * 8);
        }
#pragma unroll
        for (int t = 0; t < 6; t++) {               // B: 192 rows
            int idx = tid + t * 256, r = idx >> 3, q = idx & 7;
            CP16(ab + 18432 + r * 144 + q * 16, g_wtf + (size_t)(h * 192 + r) * 512 + d0 + q * 8);
        }
    };

    float acc[2][12][4];
#pragma unroll
    for (int a = 0; a < 2; a++)
#pragma unroll
        for (int n = 0; n < 12; n++)
#pragma unroll
            for (int c = 0; c < 4; c++) acc[a][n][c] = 0.f;

    issue(0); CPCOMMIT();
    issue(1); CPCOMMIT();
    for (int c8 = 0; c8 < 8; c8++) {
        if (c8 < 7) CPWAIT1(); else CPWAIT0();
        __syncthreads();
        if (c8 < 6) { issue(c8 + 2); CPCOMMIT(); }
        const unsigned ab = sb + (c8 % 3) * QSTG;
#pragma unroll
        for (int ks = 0; ks < 4; ks++) {
            const int kb = ks * 32;
            unsigned a0[4], a1[4];
            ldA(a0, ab, 144, m0,      kb, lane);
            ldA(a1, ab, 144, m0 + 16, kb, lane);
#pragma unroll
            for (int g = 0; g < 6; g++) {
                unsigned bf[4];
                ldB(bf, ab + 18432, 144, n0 + g * 16, kb, lane);
                mma_fp16(acc[0][2*g],   a0, bf[0], bf[1]);
                mma_fp16(acc[0][2*g+1], a0, bf[2], bf[3]);
                mma_fp16(acc[1][2*g],   a1, bf[0], bf[1]);
                mma_fp16(acc[1][2*g+1], a1, bf[2], bf[3]);
            }
        }
    }

    // writeout: q,k direct; v staged transposed in buffer-2 region (dead)
    char* vst = smc + 2 * QSTG;
#pragma unroll
    for (int mt = 0; mt < 2; mt++) {
#pragma unroll
        for (int half = 0; half < 2; half++) {
            int tl = m0 + mt * 16 + half * 8 + (lane >> 2);   // local row 0..127
            int r = row0 + tl;
            int b = r >> 11, s = r & (SLEN - 1);
#pragma unroll
            for (int nt = 0; nt < 12; nt++) {
                int col = n0 + nt * 8 + (lane & 3) * 2;
                int j = col >> 6, cc = col & 63;
                float v0 = acc[mt][nt][half * 2 + 0];
                float v1 = acc[mt][nt][half * 2 + 1];
                if (j == 0) { v0 *= QSCALE; v1 *= QSCALE; }
                if (j < 2) {
                    unsigned short* dst = (j == 0) ? g_qf : g_kf;
                    size_t base = ((size_t)(b * HNUM + h) * SLEN + s) * KDIM + cc;
                    *(unsigned*)(dst + base) = pk2(f2h(v0), f2h(v1));
                } else {   // V: [d][t] into staging
                    *(unsigned short*)(vst + (cc    ) * 272 + tl * 2) = f2h(v0);
                    *(unsigned short*)(vst + (cc + 1) * 272 + tl * 2) = f2h(v1);
                }
            }
        }
    }
    __syncthreads();
    {
        const int b = row0 >> 11, s0 = row0 & (SLEN - 1);
        const size_t vbase = ((size_t)(b * HNUM + h) * KDIM) * SLEN;
#pragma unroll
        for (int t = 0; t < 4; t++) {
            int idx = tid + t * 256, d = idx >> 4, q = idx & 15;
            *(uint4*)(g_vtf + vbase + (size_t)d * SLEN + s0 + q * 8) =
                *(const uint4*)(vst + d * 272 + q * 16);
        }
    }
}

// ================= attention (fp16; S in fp16-D; ex2 on accumulator regs) =================
// grid (16, 32), block 256. Warp (wm,wn): q-rows 32wm..+31, key half 64wn..+63.
// smem: Q 0 (18432); stage s (s=0..2) at 18432 + s*35840: K +0 (18432), V +18432 (17408).
#define ASTG0 18432
#define ASTG  35840
#define ATT_SMEM (ASTG0 + 3 * ASTG)   // 125952
__global__ __launch_bounds__(256, 1) void attn_mma() {
    extern __shared__ char smc[];
    const unsigned sb = smem_u32(smc);
    const int tid = threadIdx.x, wid = tid >> 5, lane = tid & 31;
    const int wm = wid >> 1, wn = wid & 1;
    const int m0 = wm * 32, nh = wn * 64;
    const int bh = blockIdx.y, q0 = blockIdx.x * 128;
    const int b = bh >> 3, h = bh & 7;

    const size_t kbase = (size_t)bh * SLEN * KDIM;
    const size_t vbase = (size_t)bh * KDIM * SLEN;

    auto issue_kv = [&](int it) {
        const unsigned stb = sb + ASTG0 + (it % 3) * ASTG;
        const int t0 = it * 128;
#pragma unroll
        for (int t = 0; t < 4; t++) {                 // K tile [t][d]
            int idx = tid + t * 256, r = idx >> 3, q = idx & 7;
            CP16(stb + r * 144 + q * 16, g_kf + kbase + (size_t)(t0 + r) * KDIM + q * 8);
        }
#pragma unroll
        for (int t = 0; t < 4; t++) {                 // Vt tile [d][t]
            int idx = tid + t * 256, d = idx >> 4, q = idx & 15;
            CP16(stb + 18432 + d * 272 + q * 16, g_vtf + vbase + (size_t)d * SLEN + t0 + q * 8);
        }
    };

    // prologue: Q (own group), then kv0, kv1
    {
        const size_t qb = ((size_t)bh * SLEN + q0) * KDIM;
#pragma unroll
        for (int t = 0; t < 4; t++) {
            int idx = tid + t * 256, r = idx >> 3, q = idx & 7;
            CP16(sb + r * 144 + q * 16, g_qf + qb + (size_t)r * KDIM + q * 8);
        }
        CPCOMMIT();
        issue_kv(0); CPCOMMIT();
        issue_kv(1); CPCOMMIT();
    }
    CPWAIT2();           // Q group done
    __syncthreads();

    unsigned aq[4][2][4];          // [ks][mt][frag] — Q is loop-invariant
#pragma unroll
    for (int ks = 0; ks < 4; ks++) {
        ldA(aq[ks][0], sb, 144, m0,      ks * 32, lane);
        ldA(aq[ks][1], sb, 144, m0 + 16, ks * 32, lane);
    }

    float oacc[2][8][4];
    float lsum[2][2];
#pragma unroll
    for (int mt = 0; mt < 2; mt++) {
        lsum[mt][0] = lsum[mt][1] = 0.f;
#pragma unroll
        for (int n = 0; n < 8; n++)
#pragma unroll
            for (int c = 0; c < 4; c++) oacc[mt][n][c] = 0.f;
    }

    for (int it = 0; it < 16; it++) {
        if (it < 15) CPWAIT1(); else CPWAIT0();
        __syncthreads();
        if (it < 14) { issue_kv(it + 2); CPCOMMIT(); }
        const unsigned stb = sb + ASTG0 + (it % 3) * ASTG;

        // ---- S = Q K^T in fp16-D (log2 domain); D-frag layout == PV A-frag ----
        unsigned sacc[2][8][2];
#pragma unroll
        for (int mt = 0; mt < 2; mt++)
#pragma unroll
            for (int n = 0; n < 8; n++) { sacc[mt][n][0] = 0u; sacc[mt][n][1] = 0u; }
#pragma unroll
        for (int ks = 0; ks < 4; ks++) {
            const int kb = ks * 32;
#pragma unroll
            for (int g = 0; g < 4; g++) {
                unsigned bk[4];
                ldB(bk, stb, 144, nh + g * 16, kb, lane);
                mma_fp16h(sacc[0][2*g],   aq[ks][0], bk[0], bk[1]);
                mma_fp16h(sacc[0][2*g+1], aq[ks][0], bk[2], bk[3]);
                mma_fp16h(sacc[1][2*g],   aq[ks][1], bk[0], bk[1]);
                mma_fp16h(sacc[1][2*g+1], aq[ks][1], bk[2], bk[3]);
            }
        }

        // ---- per-k16-chunk: p = 2^s via ex2 on acc regs, l from HADD2 pairs, PV ----
#pragma unroll
        for (int kc = 0; kc < 4; kc++) {
            unsigned ph[2][4];
#pragma unroll
            for (int mt = 0; mt < 2; mt++) {
                ph[mt][0] = h2ex2(sacc[mt][2*kc  ][0]);   // rows r,   keys 2c..
                ph[mt][1] = h2ex2(sacc[mt][2*kc  ][1]);   // rows r+8
                ph[mt][2] = h2ex2(sacc[mt][2*kc+1][0]);   // rows r,   keys 8+2c..
                ph[mt][3] = h2ex2(sacc[mt][2*kc+1][1]);   // rows r+8
                __half2 s0 = __hadd2(*(__half2*)&ph[mt][0], *(__half2*)&ph[mt][2]);
                __half2 s1 = __hadd2(*(__half2*)&ph[mt][1], *(__half2*)&ph[mt][3]);
                float2 f0 = __half22float2(s0);
                float2 f1 = __half22float2(s1);
                lsum[mt][0] += f0.x + f0.y;
                lsum[mt][1] += f1.x + f1.y;
            }
            const int kb = nh * 2 + kc * 32;
#pragma unroll
            for (int g = 0; g < 4; g++) {
                unsigned bf[4];
                ldB(bf, stb + 18432, 272, g * 16, kb, lane);
                mma_fp16(oacc[0][2*g],   ph[0], bf[0], bf[1]);
                mma_fp16(oacc[0][2*g+1], ph[0], bf[2], bf[3]);
                mma_fp16(oacc[1][2*g],   ph[1], bf[0], bf[1]);
                mma_fp16(oacc[1][2*g+1], ph[1], bf[2], bf[3]);
            }
        }
    }

    // ---- rowsum quad-reduce ----
#pragma unroll
    for (int mt = 0; mt < 2; mt++)
#pragma unroll
        for (int hf = 0; hf < 2; hf++) {
            float v = lsum[mt][hf];
            v += __shfl_xor_sync(0xffffffffu, v, 1);
            v += __shfl_xor_sync(0xffffffffu, v, 2);
            lsum[mt][hf] = v;
        }

    // ---- combine key-half partials via buffer-1 region (dead after it=15) ----
    float* ox = (float*)(smc + ASTG0 + ASTG);           // [128][68] fp32
    float* lx = (float*)(smc + ASTG0 + ASTG + 34816);   // [128]
    const int rq = lane >> 2;
    if (wn == 1) {
#pragma unroll
        for (int mt = 0; mt < 2; mt++) {
            int r = m0 + mt * 16 + rq;
#pragma unroll
            for (int nt = 0; nt < 8; nt++) {
                int col = nt * 8 + (lane & 3) * 2;
                ox[(r    ) * 68 + col]     = oacc[mt][nt][0];
                ox[(r    ) * 68 + col + 1] = oacc[mt][nt][1];
                ox[(r + 8) * 68 + col]     = oacc[mt][nt][2];
                ox[(r + 8) * 68 + col + 1] = oacc[mt][nt][3];
            }
            if ((lane & 3) == 0) { lx[r] = lsum[mt][0]; lx[r + 8] = lsum[mt][1]; }
        }
    }
    __syncthreads();
    if (wn == 0) {
#pragma unroll
        for (int mt = 0; mt < 2; mt++) {
            int r = m0 + mt * 16 + rq;
            const float inv0 = 1.f / (lsum[mt][0] + lx[r]);
            const float inv1 = 1.f / (lsum[mt][1] + lx[r + 8]);
            const size_t base0 = ((size_t)b * SLEN + q0 + r) * DMODEL + h * KDIM;
            const size_t base1 = base0 + 8 * DMODEL;
#pragma unroll
            for (int nt = 0; nt < 8; nt++) {
                int col = nt * 8 + (lane & 3) * 2;
                float v0 = (oacc[mt][nt][0] + ox[(r    ) * 68 + col])     * inv0;
                float v1 = (oacc[mt][nt][1] + ox[(r    ) * 68 + col + 1]) * inv0;
                float v2 = (oacc[mt][nt][2] + ox[(r + 8) * 68 + col])     * inv1;
                float v3 = (oacc[mt][nt][3] + ox[(r + 8) * 68 + col + 1]) * inv1;
                *(unsigned*)(g_cf + base0 + col) = pk2(f2h(v0), f2h(v1));
                *(unsigned*)(g_cf + base1 + col) = pk2(f2h(v2), f2h(v3));
            }
        }
    }
}

// ================= output projection (fp16 1-pass fp32-D, 256 thr, 3-stage) =================
// grid (64, 4), block 256. 8 warps as 4m x 2n: warp tile 32 x 64.
// stage: A 0 (18432), B 18432 (18432). 3 buffers.
#define OSTG 36864
#define OUT_SMEM (3 * OSTG)     // 110592
__global__ __launch_bounds__(256, 1) void outproj_mma(float* __restrict__ out) {
    extern __shared__ char smc[];
    const unsigned sb = smem_u32(smc);
    const int tid = threadIdx.x, wid = tid >> 5, lane = tid & 31;
    const int wm = wid >> 1, wn = wid & 1;
    const int row0 = blockIdx.x * 128, n0 = blockIdx.y * 128;

    auto issue = [&](int c8) {
        const unsigned ob = sb + (c8 % 3) * OSTG;
        const int e0 = c8 * 64;
#pragma unroll
        for (int t = 0; t < 4; t++) {
            int idx = tid + t * 256, r = idx >> 3, q = idx & 7;
            CP16(ob + r * 144 + q * 16, g_cf + (size_t)(row0 + r) * 512 + e0 + q * 8);
            CP16(ob + 18432 + r * 144 + q * 16, g_hktf + (size_t)(n0 + r) * 512 + e0 + q * 8);
        }
    };

    float acc[2][8][4];
#pragma unroll
    for (int a = 0; a < 2; a++)
#pragma unroll
        for (int n = 0; n < 8; n++)
#pragma unroll
            for (int c = 0; c < 4; c++) acc[a][n][c] = 0.f;

    issue(0); CPCOMMIT();
    issue(1); CPCOMMIT();
    for (int c8 = 0; c8 < 8; c8++) {
        if (c8 < 7) CPWAIT1(); else CPWAIT0();
        __syncthreads();
        if (c8 < 6) { issue(c8 + 2); CPCOMMIT(); }
        const unsigned ob = sb + (c8 % 3) * OSTG;
#pragma unroll
        for (int ks = 0; ks < 4; ks++) {
            const int kb = ks * 32;
            unsigned a0[4], a1[4];
            ldA(a0, ob, 144, wm * 32,      kb, lane);
            ldA(a1, ob, 144, wm * 32 + 16, kb, lane);
#pragma unroll
            for (int g = 0; g < 4; g++) {
                unsigned bf[4];
                ldB(bf, ob + 18432, 144, wn * 64 + g * 16, kb, lane);
                mma_fp16(acc[0][2*g],   a0, bf[0], bf[1]);
                mma_fp16(acc[0][2*g+1], a0, bf[2], bf[3]);
                mma_fp16(acc[1][2*g],   a1, bf[0], bf[1]);
                mma_fp16(acc[1][2*g+1], a1, bf[2], bf[3]);
            }
        }
    }

#pragma unroll
    for (int mt = 0; mt < 2; mt++) {
        int r0 = row0 + wm * 32 + mt * 16 + (lane >> 2);
#pragma unroll
        for (int hf = 0; hf < 2; hf++) {
            size_t base = (size_t)(r0 + hf * 8) * DMODEL + n0;
#pragma unroll
            for (int nt = 0; nt < 8; nt++) {
                int col = wn * 64 + nt * 8 + (lane & 3) * 2;
                out[base + col]     = acc[mt][nt][hf * 2 + 0];
                out[base + col + 1] = acc[mt][nt][hf * 2 + 1];
            }
        }
    }
}

// =====================================================================
extern "C" void kernel_launch(void* const* d_in, const int* in_sizes, int n_in,
                              void* d_out, int out_size)
{
    const float* x    = (const float*)d_in[0];   // (4, 2048, 512)
    const float* kern = (const float*)d_in[1];   // (24, 512, 64)
    const float* hk   = (const float*)d_in[2];   // (512, 512)
    float* out = (float*)d_out;                  // (4, 2048, 512)

    cudaFuncSetAttribute(qkv_mma,     cudaFuncAttributeMaxDynamicSharedMemorySize, QKV_SMEM);
    cudaFuncSetAttribute(attn_mma,    cudaFuncAttributeMaxDynamicSharedMemorySize, ATT_SMEM);
    cudaFuncSetAttribute(outproj_mma, cudaFuncAttributeMaxDynamicSharedMemorySize, OUT_SMEM);

    convert_all<<<CVT_XB + CVT_WB + CVT_HB, 256>>>(x, kern, hk);
    qkv_mma<<<dim3(BSROWS / 128, HNUM), 256, QKV_SMEM>>>();
    attn_mma<<<dim3(SLEN / 128, NBH), 256, ATT_SMEM>>>();
    outproj_mma<<<dim3(BSROWS / 128, DMODEL / 128), 256, OUT_SMEM>>>(out);
}